// round 6
// baseline (speedup 1.0000x reference)
#include <cuda_runtime.h>
#include <cuda_bf16.h>
#include <math.h>
#include <float.h>
#include <stdint.h>

#define BB 8
#define TT 4096
#define HH 128
#define NBLK 6
#define KK 20
#define BT (BB*TT)   // 32768
#define SX 132       // activation tile stride (floats)
#define BSTR 136     // B chunk stride (floats)

typedef unsigned long long u64;

// packed f32x2 helpers
#define FMA2(d, a, b, c) \
    asm("fma.rn.f32x2 %0, %1, %2, %3;" : "=l"(d) : "l"(a), "l"(b), "l"(c))
#define MUL2(d, a, b) \
    asm("mul.rn.f32x2 %0, %1, %2;" : "=l"(d) : "l"(a), "l"(b))
#define ADD2(d, a, b) \
    asm("add.rn.f32x2 %0, %1, %2;" : "=l"(d) : "l"(a), "l"(b))
#define BCAST2(d, s) \
    asm("mov.b64 %0, {%1, %1};" : "=l"(d) : "r"(s))
#define UNPK2(lo, hi, s) \
    asm("mov.b64 {%0, %1}, %2;" : "=r"(lo), "=r"(hi) : "l"(s))

__device__ __forceinline__ u64 pack2(float a, float b) {
    u64 r;
    asm("mov.b64 %0, {%1, %2};" : "=l"(r) : "r"(__float_as_uint(a)), "r"(__float_as_uint(b)));
    return r;
}
__device__ __forceinline__ u64 bcast2f(float a) {
    u64 r; BCAST2(r, __float_as_uint(a)); return r;
}

// tf32 mma (sm_80+ PTX, valid at target sm_103)
#define MMA_TF32(d, a, b) \
    asm volatile("mma.sync.aligned.m16n8k8.row.col.f32.tf32.tf32.f32 " \
        "{%0,%1,%2,%3}, {%4,%5,%6,%7}, {%8,%9}, {%0,%1,%2,%3};" \
        : "+f"((d)[0]), "+f"((d)[1]), "+f"((d)[2]), "+f"((d)[3]) \
        : "r"((a)[0]), "r"((a)[1]), "r"((a)[2]), "r"((a)[3]), \
          "r"((b)[0]), "r"((b)[1]))

__device__ __forceinline__ uint32_t tf32_hi(float v) {
    uint32_t h; asm("cvt.rna.tf32.f32 %0, %1;" : "=r"(h) : "f"(v));
    return h;
}

// ---------------- scratch (device globals; no allocation) ----------------
__device__ float g_net[BT * HH];   // 16 MB
__device__ float g_att[BT * HH];   // 16 MB
__device__ int   g_idx[BT * KK];
__device__ float g_dis[BT * KK];
__device__ float g_bprep[NBLK * 48 * 4096];   // 4.7 MB

// ======================= KNN ============================================
// 64 threads/block, 2 queries/thread, packed-pair candidate test.
__device__ __forceinline__ void topk_insert(float* bd, int* bi, float d, int idx)
{
    bd[KK-1] = d; bi[KK-1] = idx;
#pragma unroll
    for (int q2 = KK-1; q2 > 0; --q2) {
        if (bd[q2] < bd[q2-1]) {
            float td = bd[q2]; bd[q2] = bd[q2-1]; bd[q2-1] = td;
            int   ti = bi[q2]; bi[q2] = bi[q2-1]; bi[q2-1] = ti;
        }
    }
}

#define SIGNMASK2 0x8000000080000000ull

__global__ __launch_bounds__(64) void knn_kernel(const float* __restrict__ p)
{
    const int b   = blockIdx.y;
    const int tid = threadIdx.x;
    const int qA  = blockIdx.x * 128 + tid;
    const int qB  = qA + 64;
    const float* pb = p + (size_t)b * TT * 3;

    const float axA = pb[qA*3+0], ayA = pb[qA*3+1], azA = pb[qA*3+2];
    const float axB = pb[qB*3+0], ayB = pb[qB*3+1], azB = pb[qB*3+2];
    const float sqqA = axA*axA + ayA*ayA + azA*azA;
    const float sqqB = axB*axB + ayB*ayB + azB*azB;

    const u64 qxA2 = bcast2f(axA), qyA2 = bcast2f(ayA), qzA2 = bcast2f(azA);
    const u64 qxB2 = bcast2f(axB), qyB2 = bcast2f(ayB), qzB2 = bcast2f(azB);
    const u64 NEG2 = bcast2f(-2.0f);

    float bdA[KK], bdB[KK];
    int   biA[KK], biB[KK];
#pragma unroll
    for (int k = 0; k < KK; ++k) {
        bdA[k] = FLT_MAX; biA[k] = 0;
        bdB[k] = FLT_MAX; biB[k] = 0;
    }
    u64 ntA2 = bcast2f(-FLT_MAX);
    u64 ntB2 = bcast2f(-FLT_MAX);

    __shared__ ulonglong2 spXY[512];   // (x-pair, y-pair)
    __shared__ ulonglong2 spZW[512];   // (z-pair, |.|^2-pair)

    for (int s0 = 0; s0 < TT; s0 += 1024) {
        __syncthreads();
        for (int l = tid; l < 512; l += 64) {
            const float* q = pb + (size_t)(s0 + 2*l) * 3;
            float x0 = q[0], y0 = q[1], z0 = q[2];
            float x1 = q[3], y1 = q[4], z1 = q[5];
            spXY[l] = make_ulonglong2(pack2(x0, x1), pack2(y0, y1));
            spZW[l] = make_ulonglong2(pack2(z0, z1),
                                      pack2(x0*x0 + y0*y0 + z0*z0,
                                            x1*x1 + y1*y1 + z1*z1));
        }
        __syncthreads();
#pragma unroll 4
        for (int l = 0; l < 512; ++l) {
            ulonglong2 xy = spXY[l];
            ulonglong2 zw = spZW[l];
            // query A
            u64 dA; MUL2(dA, qzA2, zw.x);
            FMA2(dA, qyA2, xy.y, dA);
            FMA2(dA, qxA2, xy.x, dA);
            u64 eA; FMA2(eA, dA, NEG2, zw.y);     // d2' = |s|^2 - 2 q.s
            u64 tA; ADD2(tA, eA, ntA2);
            if (tA & SIGNMASK2) {
                unsigned lo, hi; UNPK2(lo, hi, eA);
                float d0 = __uint_as_float(lo) + sqqA;
                if (d0 < bdA[KK-1]) topk_insert(bdA, biA, d0, s0 + 2*l);
                float d1 = __uint_as_float(hi) + sqqA;
                if (d1 < bdA[KK-1]) topk_insert(bdA, biA, d1, s0 + 2*l + 1);
                ntA2 = bcast2f(sqqA - bdA[KK-1]);
            }
            // query B
            u64 dB; MUL2(dB, qzB2, zw.x);
            FMA2(dB, qyB2, xy.y, dB);
            FMA2(dB, qxB2, xy.x, dB);
            u64 eB; FMA2(eB, dB, NEG2, zw.y);
            u64 tB; ADD2(tB, eB, ntB2);
            if (tB & SIGNMASK2) {
                unsigned lo, hi; UNPK2(lo, hi, eB);
                float d0 = __uint_as_float(lo) + sqqB;
                if (d0 < bdB[KK-1]) topk_insert(bdB, biB, d0, s0 + 2*l);
                float d1 = __uint_as_float(hi) + sqqB;
                if (d1 < bdB[KK-1]) topk_insert(bdB, biB, d1, s0 + 2*l + 1);
                ntB2 = bcast2f(sqqB - bdB[KK-1]);
            }
        }
    }

    const size_t oA = ((size_t)b * TT + qA) * KK;
    const size_t oB = ((size_t)b * TT + qB) * KK;
#pragma unroll
    for (int k = 0; k < KK; ++k) {
        g_idx[oA + k] = biA[k];
        g_dis[oA + k] = sqrtf(fmaxf(bdA[k], 1e-12f));
        g_idx[oB + k] = biB[k];
        g_dis[oB + k] = sqrtf(fmaxf(bdB[k], 1e-12f));
    }
}

// ======================= positional encoding ============================
__global__ __launch_bounds__(256) void pos_kernel(const float* __restrict__ p,
                                                  const float* __restrict__ W_pos,
                                                  const float* __restrict__ b_pos)
{
    int gid = blockIdx.x * 256 + threadIdx.x;
    int t = gid >> 7;
    int h = gid & 127;
    const float* pp = p + (size_t)t * 3;
    float v = b_pos[h];
    v = fmaf(pp[0], W_pos[h],        v);
    v = fmaf(pp[1], W_pos[HH + h],   v);
    v = fmaf(pp[2], W_pos[2*HH + h], v);
    g_net[gid] = v;
}

// ======================= attention (gather + softmax) ===================
__global__ __launch_bounds__(256) void attn_kernel(const float* __restrict__ p,
                                                   const float* __restrict__ wc,
                                                   const float* __restrict__ bc)
{
    const int warp = threadIdx.x >> 5;
    const int lane = threadIdx.x & 31;
    const int t  = blockIdx.x * 8 + warp;
    const int b  = t >> 12;
    const int tt = t & (TT - 1);
    const float* pb = p + (size_t)b * TT * 3;

    const float q0 = pb[tt*3+0], q1 = pb[tt*3+1], q2 = pb[tt*3+2];
    const float w0 = wc[0], w1 = wc[1], w2 = wc[2], w3 = wc[3];
    const float w4 = wc[4], w5 = wc[5], w6 = wc[6], bcv = bc[0];

    float s = -FLT_MAX;
    int   j = 0;
    if (lane < KK) {
        size_t o = (size_t)t * KK + lane;
        j = g_idx[o];
        float d = g_dis[o];
        const float* px = pb + (size_t)j * 3;
        s = bcv;
        s = fmaf(w0, d,     s);
        s = fmaf(w1, px[0], s);
        s = fmaf(w2, px[1], s);
        s = fmaf(w3, px[2], s);
        s = fmaf(w4, q0,    s);
        s = fmaf(w5, q1,    s);
        s = fmaf(w6, q2,    s);
    }
    float m = s;
#pragma unroll
    for (int off = 16; off; off >>= 1)
        m = fmaxf(m, __shfl_xor_sync(0xffffffffu, m, off));
    float e = (lane < KK) ? expf(s - m) : 0.0f;
    float sum = e;
#pragma unroll
    for (int off = 16; off; off >>= 1)
        sum += __shfl_xor_sync(0xffffffffu, sum, off);
    const float inv = 1.0f / sum;

    float4 acc = make_float4(0.f, 0.f, 0.f, 0.f);
    const float* nb = g_net + (size_t)b * TT * HH;
#pragma unroll
    for (int k = 0; k < KK; ++k) {
        float wk = __shfl_sync(0xffffffffu, e, k) * inv;
        int   jk = __shfl_sync(0xffffffffu, j, k);
        float4 v = *(const float4*)(nb + (size_t)jk * HH + lane * 4);
        acc.x = fmaf(wk, v.x, acc.x);
        acc.y = fmaf(wk, v.y, acc.y);
        acc.z = fmaf(wk, v.z, acc.z);
        acc.w = fmaf(wk, v.w, acc.w);
    }
    *(float4*)(g_att + (size_t)t * HH + lane * 4) = acc;
}

// ======================= weight prep ====================================
// 48 K16-chunk slots per block:
//   Wo: 0..7, W0: 8..23 (K=256), W1: 24..31, Ws: 32..47 (K=256)
__global__ __launch_bounds__(256) void prep_weights(
    const float* __restrict__ Wo, const float* __restrict__ W0,
    const float* __restrict__ W1, const float* __restrict__ Ws, int base)
{
    const int blk = blockIdx.y;
    const int slot = blockIdx.x + base;
    const float* W; int ck;
    if (slot < 8)       { W = Wo + (size_t)blk*128*128; ck = slot; }
    else if (slot < 24) { W = W0 + (size_t)blk*256*128; ck = slot-8; }
    else if (slot < 32) { W = W1 + (size_t)blk*128*128; ck = slot-24; }
    else                { W = Ws + (size_t)blk*256*128; ck = slot-32; }
    float* img = g_bprep + ((size_t)blk*48 + slot)*4096;

    for (int idx = threadIdx.x; idx < 2048; idx += 256) {
        int kk = idx >> 7, n = idx & 127;
        float v = W[(size_t)(ck*16 + kk)*128 + n];
        uint32_t h = tf32_hi(v);
        float hv = __uint_as_float(h);
        uint32_t l = tf32_hi(v - hv);
        img[idx]        = hv;
        img[2048 + idx] = __uint_as_float(l);
    }
}

// ======================= tensor-core resnet =============================
__device__ __forceinline__ void init_acc(float acc[2][8][4],
                                         const float* __restrict__ bias,
                                         int nb, int tig)
{
#pragma unroll
    for (int j = 0; j < 8; ++j) {
        int col0 = nb + j*8 + 2*tig;
        float b0v = __ldg(bias + col0);
        float b1v = __ldg(bias + col0 + 1);
#pragma unroll
        for (int mt = 0; mt < 2; ++mt) {
            acc[mt][j][0] = b0v; acc[mt][j][1] = b1v;
            acc[mt][j][2] = b0v; acc[mt][j][3] = b1v;
        }
    }
}

template<bool RELU>
__device__ __forceinline__ void gemm_tc(
    const float* As, const float* __restrict__ prep, int nchunks,
    float acc[2][8][4], float* Bs, int tid, int rb, int nb)
{
    const int lane = tid & 31;
    const int gid = lane >> 2, tig = lane & 3;
    const int kk0 = tid >> 5, n40 = (tid & 31) << 2;

    // prefetch chunk 0
    float4 pre[4];
    pre[0] = ((const float4*)prep)[tid];
    pre[1] = ((const float4*)prep)[tid + 256];
    pre[2] = ((const float4*)(prep + 2048))[tid];
    pre[3] = ((const float4*)(prep + 2048))[tid + 256];

    for (int c = 0; c < nchunks; ++c) {
        __syncthreads();
        *(float4*)(Bs + kk0*BSTR + n40)                 = pre[0];
        *(float4*)(Bs + (kk0+8)*BSTR + n40)             = pre[1];
        *(float4*)(Bs + 16*BSTR + kk0*BSTR + n40)       = pre[2];
        *(float4*)(Bs + 16*BSTR + (kk0+8)*BSTR + n40)   = pre[3];
        __syncthreads();
        if (c + 1 < nchunks) {
            const float* src = prep + (size_t)(c+1) * 4096;
            pre[0] = ((const float4*)src)[tid];
            pre[1] = ((const float4*)src)[tid + 256];
            pre[2] = ((const float4*)(src + 2048))[tid];
            pre[3] = ((const float4*)(src + 2048))[tid + 256];
        }

#pragma unroll
        for (int ks = 0; ks < 2; ++ks) {
            const int k0 = c*16 + ks*8;
            uint32_t Ah[2][4], Al[2][4];
#pragma unroll
            for (int mt = 0; mt < 2; ++mt) {
                const int r0 = rb + mt*16 + gid;
                float f[4];
                f[0] = As[(size_t)r0*SX + k0 + tig];
                f[1] = As[(size_t)(r0+8)*SX + k0 + tig];
                f[2] = As[(size_t)r0*SX + k0 + tig + 4];
                f[3] = As[(size_t)(r0+8)*SX + k0 + tig + 4];
#pragma unroll
                for (int i = 0; i < 4; ++i) {
                    float v = RELU ? fmaxf(f[i], 0.0f) : f[i];
                    uint32_t h = tf32_hi(v);
                    Ah[mt][i] = h;
                    Al[mt][i] = tf32_hi(v - __uint_as_float(h));
                }
            }
#pragma unroll
            for (int j = 0; j < 8; ++j) {
                const int nbase = nb + j*8 + gid;
                const float* bk0 = Bs + (ks*8 + tig)*BSTR + nbase;
                const float* bk1 = Bs + (ks*8 + tig + 4)*BSTR + nbase;
                uint32_t bh[2], bl[2];
                bh[0] = __float_as_uint(bk0[0]);
                bh[1] = __float_as_uint(bk1[0]);
                bl[0] = __float_as_uint(bk0[16*BSTR]);
                bl[1] = __float_as_uint(bk1[16*BSTR]);
#pragma unroll
                for (int mt = 0; mt < 2; ++mt) {
                    MMA_TF32(acc[mt][j], Ah[mt], bh);
                    MMA_TF32(acc[mt][j], Al[mt], bh);
                    MMA_TF32(acc[mt][j], Ah[mt], bl);
                }
            }
        }
    }
}

template<bool RELU>
__device__ __forceinline__ void store_acc_smem(float acc[2][8][4], float* tile,
                                               int rb, int nb, int lane)
{
    const int gid = lane >> 2, tig = lane & 3;
#pragma unroll
    for (int mt = 0; mt < 2; ++mt) {
        const int rg = rb + mt*16 + gid;
#pragma unroll
        for (int j = 0; j < 8; ++j) {
            const int col0 = nb + j*8 + 2*tig;
            float v0 = acc[mt][j][0], v1 = acc[mt][j][1];
            float v2 = acc[mt][j][2], v3 = acc[mt][j][3];
            if (RELU) {
                v0 = fmaxf(v0, 0.f); v1 = fmaxf(v1, 0.f);
                v2 = fmaxf(v2, 0.f); v3 = fmaxf(v3, 0.f);
            }
            *(float2*)(tile + (size_t)rg*SX + col0)     = make_float2(v0, v1);
            *(float2*)(tile + (size_t)(rg+8)*SX + col0) = make_float2(v2, v3);
        }
    }
}

__global__ __launch_bounds__(256) void resnet_tc(
    int blk,
    const float* __restrict__ b0, const float* __restrict__ b1,
    const float* __restrict__ bo, int add_res)
{
    extern __shared__ float sm[];
    float* xs  = sm;                 // [128][SX] net (x)
    float* as_ = sm + 128*SX;        // [128][SX] a1
    float* hs  = sm + 2*128*SX;      // [128][SX] att, then relu(h)
    float* Bs  = sm + 3*128*SX;      // [32][BSTR] hi+lo chunk

    const int tid = threadIdx.x;
    const int wid = tid >> 5, lane = tid & 31;
    const int rb = (wid & 3) * 32;
    const int nb = (wid >> 2) * 64;
    const int gid = lane >> 2, tig = lane & 3;
    const size_t t0 = (size_t)blockIdx.x * 128;
    const float* prep = g_bprep + (size_t)blk * 48 * 4096;

    for (int q = tid; q < 128 * 32; q += 256) {
        int r = q >> 5, c = (q & 31) << 2;
        *(float4*)(xs + r * SX + c) = *(const float4*)(g_net + (t0 + r) * HH + c);
        *(float4*)(hs + r * SX + c) = *(const float4*)(g_att + (t0 + r) * HH + c);
    }

    float acc[2][8][4];

    // ---- GEMM1: a1 = att @ Wo^T + bo -> as_
    init_acc(acc, bo, nb, tig);
    gemm_tc<false>(hs, prep + 0*4096, 8, acc, Bs, tid, rb, nb);
    store_acc_smem<false>(acc, as_, rb, nb, lane);

    // ---- GEMM2: h = relu(relu([x|a1]) @ W0 + b0) -> hs
    init_acc(acc, b0, nb, tig);
    gemm_tc<true>(xs,  prep + 8*4096,  8, acc, Bs, tid, rb, nb);
    gemm_tc<true>(as_, prep + 16*4096, 8, acc, Bs, tid, rb, nb);
    __syncthreads();
    store_acc_smem<true>(acc, hs, rb, nb, lane);

    // ---- GEMM3+4: out = h @ W1^T + b1 + [x|a1] @ Ws^T [+ residual x]
    init_acc(acc, b1, nb, tig);
    gemm_tc<false>(hs,  prep + 24*4096, 8, acc, Bs, tid, rb, nb);
    gemm_tc<false>(xs,  prep + 32*4096, 8, acc, Bs, tid, rb, nb);
    gemm_tc<false>(as_, prep + 40*4096, 8, acc, Bs, tid, rb, nb);

#pragma unroll
    for (int mt = 0; mt < 2; ++mt) {
        const int rg = rb + mt*16 + gid;
#pragma unroll
        for (int j = 0; j < 8; ++j) {
            const int col0 = nb + j*8 + 2*tig;
            float v0 = acc[mt][j][0], v1 = acc[mt][j][1];
            float v2 = acc[mt][j][2], v3 = acc[mt][j][3];
            if (add_res) {
                float2 r0 = *(const float2*)(xs + (size_t)rg*SX + col0);
                float2 r1 = *(const float2*)(xs + (size_t)(rg+8)*SX + col0);
                v0 += r0.x; v1 += r0.y; v2 += r1.x; v3 += r1.y;
            }
            *(float2*)(g_net + (t0 + rg) * HH + col0)     = make_float2(v0, v1);
            *(float2*)(g_net + (t0 + rg + 8) * HH + col0) = make_float2(v2, v3);
        }
    }
}

// ======================= final projection (scalar, FFMA2) ===============
__device__ __forceinline__ void init_bias_f(u64 acc[8][4], const float* __restrict__ bias, int nb)
{
    ulonglong2 q0 = *(const ulonglong2*)(bias + nb);
    ulonglong2 q1 = *(const ulonglong2*)(bias + nb + 4);
#pragma unroll
    for (int r = 0; r < 8; ++r) {
        acc[r][0] = q0.x; acc[r][1] = q0.y; acc[r][2] = q1.x; acc[r][3] = q1.y;
    }
}

__global__ __launch_bounds__(256) void final_kernel(const float* __restrict__ W_c,
                                                    const float* __restrict__ b_c,
                                                    float* __restrict__ out)
{
    extern __shared__ float sm[];
    float* xs = sm;              // [128][SX]
    float* ws = sm + 128 * SX;   // [32][128]

    const int tid = threadIdx.x;
    const int tx = tid & 15;
    const int ty = tid >> 4;
    const int nb = tx * 8;
    const int rb = ty * 8;
    const size_t t0 = (size_t)blockIdx.x * 128;

    for (int q = tid; q < 128 * 32; q += 256) {
        int r = q >> 5, c = (q & 31) << 2;
        *(float4*)(xs + r * SX + c) = *(const float4*)(g_net + (t0 + r) * HH + c);
    }

    u64 acc[8][4];
    init_bias_f(acc, b_c, nb);

    for (int kt = 0; kt < 128; kt += 32) {
        __syncthreads();
        for (int q = tid; q < 1024; q += 256) {
            int kk = q >> 5, c = (q & 31) << 2;
            *(float4*)(ws + kk * 128 + c) = *(const float4*)(W_c + (size_t)(kt + kk) * 128 + c);
        }
        __syncthreads();
#pragma unroll 1
        for (int k4 = 0; k4 < 8; ++k4) {
            float4 a4[8];
#pragma unroll
            for (int r = 0; r < 8; ++r)
                a4[r] = *(const float4*)(xs + (rb + r) * SX + kt + k4 * 4);
#pragma unroll
            for (int j = 0; j < 4; ++j) {
                int kk = k4 * 4 + j;
                ulonglong2 b0v = *(const ulonglong2*)(ws + kk * 128 + nb);
                ulonglong2 b1v = *(const ulonglong2*)(ws + kk * 128 + nb + 4);
#pragma unroll
                for (int r = 0; r < 8; ++r) {
                    float a = ((const float*)&a4[r])[j];
                    u64 aa; BCAST2(aa, __float_as_uint(a));
                    FMA2(acc[r][0], aa, b0v.x, acc[r][0]);
                    FMA2(acc[r][1], aa, b0v.y, acc[r][1]);
                    FMA2(acc[r][2], aa, b1v.x, acc[r][2]);
                    FMA2(acc[r][3], aa, b1v.y, acc[r][3]);
                }
            }
        }
    }
#pragma unroll
    for (int r = 0; r < 8; ++r) {
        *(ulonglong2*)(out + (t0 + rb + r) * HH + nb)     = make_ulonglong2(acc[r][0], acc[r][1]);
        *(ulonglong2*)(out + (t0 + rb + r) * HH + nb + 4) = make_ulonglong2(acc[r][2], acc[r][3]);
    }
}

// ======================= launch =========================================
extern "C" void kernel_launch(void* const* d_in, const int* in_sizes, int n_in,
                              void* d_out, int out_size)
{
    const float* p      = (const float*)d_in[0];
    const float* W_pos  = (const float*)d_in[1];
    const float* b_pos  = (const float*)d_in[2];
    const float* blk_W0 = (const float*)d_in[3];
    const float* blk_b0 = (const float*)d_in[4];
    const float* blk_W1 = (const float*)d_in[5];
    const float* blk_b1 = (const float*)d_in[6];
    const float* blk_Ws = (const float*)d_in[7];
    const float* att_Wc = (const float*)d_in[8];
    const float* att_bc = (const float*)d_in[9];
    const float* att_Wo = (const float*)d_in[10];
    const float* att_bo = (const float*)d_in[11];
    const float* W_c    = (const float*)d_in[12];
    const float* b_c    = (const float*)d_in[13];
    float* out = (float*)d_out;

    const int RES_SMEM = (3 * 128 * SX + 32 * BSTR) * 4;   // 220,160 B
    const int FIN_SMEM = (128 * SX + 32 * 128) * 4;        //  83,968 B
    cudaFuncSetAttribute(resnet_tc,   cudaFuncAttributeMaxDynamicSharedMemorySize, RES_SMEM);
    cudaFuncSetAttribute(final_kernel, cudaFuncAttributeMaxDynamicSharedMemorySize, FIN_SMEM);

    // launch order chosen so ncu (-s 5 -c 1) captures resnet_tc at index 5
    knn_kernel<<<dim3(TT / 128, BB), 64>>>(p);
    pos_kernel<<<(BT * HH) / 256, 256>>>(p, W_pos, b_pos);
    prep_weights<<<dim3(24, NBLK), 256>>>(att_Wo, blk_W0, blk_W1, blk_Ws, 0);
    prep_weights<<<dim3(24, NBLK), 256>>>(att_Wo, blk_W0, blk_W1, blk_Ws, 24);

    for (int i = 0; i < NBLK; ++i) {
        attn_kernel<<<BT / 8, 256>>>(p, att_Wc + (size_t)i * 7, att_bc + i);
        resnet_tc<<<BT / 128, 256, RES_SMEM>>>(
            i, blk_b0 + (size_t)i * 128, blk_b1 + (size_t)i * 128,
            att_bo + (size_t)i * 128, i > 0 ? 1 : 0);
    }
    final_kernel<<<BT / 128, 256, FIN_SMEM>>>(W_c, b_c, out);
}